// round 7
// baseline (speedup 1.0000x reference)
#include <cuda_runtime.h>
#include <math.h>

#define NN   20000
#define DIN  1024
#define DOU  64
#define NE   320000
#define SZ   (NN*DOU)          // 1,280,000 floats per [N,64] buffer

// Output layout (flattened tuple, float32):
//   hiden_emb [N,64], h [N,1024], ret [N,1], ret_a [N,1], mean [N,1024], disp [N,1024]
#define OFF_HIDEN 0
#define OFF_H     ((size_t)SZ)
#define OFF_RET   (OFF_H + (size_t)NN*DIN)
#define OFF_RETA  (OFF_RET + NN)
#define OFF_MEAN  (OFF_RETA + NN)
#define OFF_DISP  (OFF_MEAN + (size_t)NN*DIN)

// Scratch
__device__ float g_z0[SZ];
__device__ float g_za0[SZ];
__device__ float g_zaacc[SZ];
__device__ float g_zsacc[SZ];
__device__ float g_t[SZ];

// ---------------------------------------------------------------------------
// f32x2 packed-FMA helpers (FFMA2 — 2x FFMA throughput, PTX-only)
// ---------------------------------------------------------------------------
__device__ __forceinline__ void fma2(unsigned long long& d,
                                     unsigned long long a, unsigned long long b) {
    asm("fma.rn.f32x2 %0, %1, %2, %0;" : "+l"(d) : "l"(a), "l"(b));
}
__device__ __forceinline__ unsigned long long pack2(float x, float y) {
    unsigned long long r;
    asm("mov.b64 %0, {%1, %2};" : "=l"(r) : "f"(x), "f"(y));
    return r;
}
__device__ __forceinline__ void unpack2(unsigned long long v, float& lo, float& hi) {
    asm("mov.b64 {%0, %1}, %2;" : "=f"(lo), "=f"(hi) : "l"(v));
}
__device__ __forceinline__ void red4(float* p, float a, float b, float c, float d) {
    asm volatile("red.global.add.v4.f32 [%0], {%1,%2,%3,%4};"
                 :: "l"(p), "f"(a), "f"(b), "f"(c), "f"(d) : "memory");
}

// ---------------------------------------------------------------------------
// Input GEMM body: C[64-row tile, 64] = A[.,1024] @ B[1024,64]
// 128 threads, 8x4 micro-tile, f32x2 row-pair packing, k-major A smem.
// ---------------------------------------------------------------------------
__device__ __forceinline__ void gemm64_body(const float* __restrict__ A,
                                            const float* __restrict__ B,
                                            float* __restrict__ C, int bx) {
    __shared__ float As[32 * 64];   // [k][row]
    __shared__ float Bs[32 * 64];   // [k][col]

    int tid = threadIdx.x;
    int rowBase = bx * 64;
    int tx = tid & 15;
    int ty = tid >> 4;

    unsigned long long acc[4][4];
#pragma unroll
    for (int i = 0; i < 4; i++)
#pragma unroll
        for (int j = 0; j < 4; j++) acc[i][j] = 0ull;

    int ar = tid >> 1;
    int ak = (tid & 1) * 16;
    bool aval = (rowBase + ar) < NN;
    const float* arow = A + (size_t)(rowBase + ar) * DIN + ak;

    for (int k0 = 0; k0 < DIN; k0 += 32) {
#pragma unroll
        for (int j = 0; j < 4; j++) {
            float4 v = aval ? *(const float4*)(arow + k0 + 4 * j)
                            : make_float4(0.f, 0.f, 0.f, 0.f);
            int kb = ak + 4 * j;
            As[(kb + 0) * 64 + ar] = v.x;
            As[(kb + 1) * 64 + ar] = v.y;
            As[(kb + 2) * 64 + ar] = v.z;
            As[(kb + 3) * 64 + ar] = v.w;
        }
        const float4* bsrc = (const float4*)(B + (size_t)k0 * DOU);
#pragma unroll
        for (int j = 0; j < 4; j++)
            ((float4*)Bs)[tid + 128 * j] = bsrc[tid + 128 * j];

        __syncthreads();

#pragma unroll 8
        for (int kk = 0; kk < 32; kk++) {
            const ulonglong2* ap = (const ulonglong2*)&As[kk * 64 + ty * 8];
            ulonglong2 aA = ap[0];
            ulonglong2 aB = ap[1];
            float4 bv = *(const float4*)&Bs[kk * 64 + tx * 4];
            unsigned long long b0 = pack2(bv.x, bv.x);
            unsigned long long b1 = pack2(bv.y, bv.y);
            unsigned long long b2 = pack2(bv.z, bv.z);
            unsigned long long b3 = pack2(bv.w, bv.w);
            fma2(acc[0][0], aA.x, b0); fma2(acc[0][1], aA.x, b1);
            fma2(acc[0][2], aA.x, b2); fma2(acc[0][3], aA.x, b3);
            fma2(acc[1][0], aA.y, b0); fma2(acc[1][1], aA.y, b1);
            fma2(acc[1][2], aA.y, b2); fma2(acc[1][3], aA.y, b3);
            fma2(acc[2][0], aB.x, b0); fma2(acc[2][1], aB.x, b1);
            fma2(acc[2][2], aB.x, b2); fma2(acc[2][3], aB.x, b3);
            fma2(acc[3][0], aB.y, b0); fma2(acc[3][1], aB.y, b1);
            fma2(acc[3][2], aB.y, b2); fma2(acc[3][3], aB.y, b3);
        }
        __syncthreads();
    }

#pragma unroll
    for (int rp = 0; rp < 4; rp++) {
        float l0, h0, l1, h1, l2, h2, l3, h3;
        unpack2(acc[rp][0], l0, h0);
        unpack2(acc[rp][1], l1, h1);
        unpack2(acc[rp][2], l2, h2);
        unpack2(acc[rp][3], l3, h3);
        int r0 = rowBase + ty * 8 + rp * 2;
        if (r0 < NN)
            *(float4*)&C[(size_t)r0 * DOU + tx * 4] = make_float4(l0, l1, l2, l3);
        if (r0 + 1 < NN)
            *(float4*)&C[(size_t)(r0 + 1) * DOU + tx * 4] = make_float4(h0, h1, h2, h3);
    }
}

#define GEMM_BLKS 313   // ceil(20000/64)
#define ZERO_BLKS 256

// Phase 1: z0 = feat@W1 ; za0 = feat_a@W1 ; zero the 4 accumulators
__global__ __launch_bounds__(128) void k_phase1(
        const float* __restrict__ feat, const float* __restrict__ feat_a,
        const float* __restrict__ W1,
        float* __restrict__ z0, float* __restrict__ za0,
        float4* __restrict__ zout, float4* __restrict__ zaacc,
        float4* __restrict__ zsacc, float4* __restrict__ t) {
    int b = blockIdx.x;
    if (b < GEMM_BLKS) {
        gemm64_body(feat, W1, z0, b);
    } else if (b < 2 * GEMM_BLKS) {
        gemm64_body(feat_a, W1, za0, b - GEMM_BLKS);
    } else {
        int i = (b - 2 * GEMM_BLKS) * 128 + threadIdx.x;
        int stride = ZERO_BLKS * 128;
        float4 zv = make_float4(0.f, 0.f, 0.f, 0.f);
        for (int j = i; j < SZ / 4; j += stride) {
            zout[j] = zv; zaacc[j] = zv; zsacc[j] = zv; t[j] = zv;
        }
    }
}

// ---------------------------------------------------------------------------
// Wide-GEMM bodies (16 rows x 256 cols per block, f32x2 k-pair packing)
// ---------------------------------------------------------------------------
__device__ __forceinline__ void wide_accum(const float* __restrict__ X,
                                           const float* __restrict__ W2,
                                           int b, unsigned long long* acc,
                                           int& col, int& rowBase) {
    __shared__ float xs[16 * 64];
    int tid = threadIdx.x;
    col = (b & 3) * 256 + tid;
    rowBase = (b >> 2) * 16;
    ((float4*)xs)[tid] = ((const float4*)(X + (size_t)rowBase * DOU))[tid];
    __syncthreads();

#pragma unroll
    for (int r = 0; r < 16; r++) acc[r] = 0ull;

#pragma unroll
    for (int k0 = 0; k0 < 64; k0 += 4) {
        float w0 = W2[(size_t)(k0 + 0) * DIN + col];
        float w1 = W2[(size_t)(k0 + 1) * DIN + col];
        float w2 = W2[(size_t)(k0 + 2) * DIN + col];
        float w3 = W2[(size_t)(k0 + 3) * DIN + col];
        unsigned long long wp0 = pack2(w0, w1);
        unsigned long long wp1 = pack2(w2, w3);
#pragma unroll
        for (int r = 0; r < 16; r++) {
            ulonglong2 xv = *(const ulonglong2*)&xs[r * 64 + k0];
            fma2(acc[r], xv.x, wp0);
            fma2(acc[r], xv.y, wp1);
        }
    }
}

// ---------------------------------------------------------------------------
// SpMM bodies (16 threads/edge, red.global.add.v4)
// ---------------------------------------------------------------------------
__device__ __forceinline__ void spmm_dual_body(unsigned idx,
        const int* __restrict__ row, const int* __restrict__ col,
        const float* __restrict__ vals,
        const float* __restrict__ x1, float* y1,
        const float* __restrict__ x2, float* y2) {
    unsigned e = idx >> 4;
    if (e >= NE) return;
    int lane4 = (idx & 15) << 2;
    int r = __ldg(&row[e]), c = __ldg(&col[e]);
    float v = __ldg(&vals[e]);

    const float4 a = __ldg((const float4*)&x1[(size_t)c * DOU + lane4]);
    red4(&y1[(size_t)r * DOU + lane4], v * a.x, v * a.y, v * a.z, v * a.w);

    const float4 bb = __ldg((const float4*)&x2[(size_t)c * DOU + lane4]);
    red4(&y2[(size_t)r * DOU + lane4], v * bb.x, v * bb.y, v * bb.z, v * bb.w);
}

__device__ __forceinline__ void spmm_single_body(unsigned idx,
        const int* __restrict__ row, const int* __restrict__ col,
        const float* __restrict__ vals,
        const float* __restrict__ x1, float* y1) {
    unsigned e = idx >> 4;
    if (e >= NE) return;
    int lane4 = (idx & 15) << 2;
    int r = __ldg(&row[e]), c = __ldg(&col[e]);
    float v = __ldg(&vals[e]);

    const float4 a = __ldg((const float4*)&x1[(size_t)c * DOU + lane4]);
    red4(&y1[(size_t)r * DOU + lane4], v * a.x, v * a.y, v * a.z, v * a.w);
}

#define MD_BLKS   5000     // meandisp: (1024/256) x (20000/16)
#define SP_BLKS   20000    // NE*16/256

// Phase 2 (fused, independent work): mean/disp from z0@W2  ||  z = A z0,
// zaacc = A za0  ||  zsacc = A_a za0
__global__ __launch_bounds__(256) void k_phase2(
        const int* __restrict__ row,  const int* __restrict__ col,
        const float* __restrict__ vals,
        const int* __restrict__ row_a, const int* __restrict__ col_a,
        const float* __restrict__ vals_a,
        const float* __restrict__ z0, const float* __restrict__ za0,
        float* __restrict__ zout, float* __restrict__ zaacc,
        float* __restrict__ zsacc,
        const float* __restrict__ W2,
        float* __restrict__ meanout, float* __restrict__ dispout) {
    int b = blockIdx.x;
    if (b < MD_BLKS) {
        unsigned long long acc[16];
        int c, rowBase;
        wide_accum(z0, W2, b, acc, c, rowBase);
#pragma unroll
        for (int r = 0; r < 16; r++) {
            size_t o = (size_t)(rowBase + r) * DIN + c;
            float lo, hi;
            unpack2(acc[r], lo, hi);
            float x = lo + hi;
            __stcs(&meanout[o], fminf(fmaxf(__expf(x), 1e-5f), 1e6f));
            float sp = fmaxf(x, 0.f) + __logf(1.f + __expf(-fabsf(x)));
            __stcs(&dispout[o], fminf(fmaxf(sp, 1e-4f), 1e4f));
        }
    } else if (b < MD_BLKS + SP_BLKS) {
        unsigned idx = (unsigned)(b - MD_BLKS) * 256u + threadIdx.x;
        spmm_dual_body(idx, row, col, vals, z0, zout, za0, zaacc);
    } else {
        unsigned idx = (unsigned)(b - MD_BLKS - SP_BLKS) * 256u + threadIdx.x;
        spmm_single_body(idx, row_a, col_a, vals_a, za0, zsacc);
    }
}

// Phase 3: t = A z
__global__ __launch_bounds__(256) void k_phase3(
        const int* __restrict__ row, const int* __restrict__ col,
        const float* __restrict__ vals,
        const float* __restrict__ z, float* __restrict__ t) {
    unsigned idx = blockIdx.x * 256u + threadIdx.x;
    spmm_single_body(idx, row, col, vals, z, t);
}

#define BI_BLKS 2500   // NN/8

// Phase 4 (fused): h = t@W2  ||  bilinear discriminators
__global__ __launch_bounds__(256) void k_phase4(
        const float* __restrict__ T, const float* __restrict__ W2,
        float* __restrict__ hout,
        const float* __restrict__ z, const float* __restrict__ za,
        const float* __restrict__ zsv,
        const float* __restrict__ W, const float* __restrict__ bptr,
        float* __restrict__ ret, float* __restrict__ reta) {
    int b = blockIdx.x;
    if (b < MD_BLKS) {
        unsigned long long acc[16];
        int c, rowBase;
        wide_accum(T, W2, b, acc, c, rowBase);
#pragma unroll
        for (int r = 0; r < 16; r++) {
            size_t o = (size_t)(rowBase + r) * DIN + c;
            float lo, hi;
            unpack2(acc[r], lo, hi);
            __stcs(&hout[o], lo + hi);
        }
    } else {
        __shared__ float Ws[64 * 65];
        __shared__ float ce[8][64], ca[8][64], cs[8][64];

        int tid = threadIdx.x;
        for (int idx = tid; idx < 4096; idx += 256) {
            int d = idx >> 6, k = idx & 63;
            Ws[d * 65 + k] = W[idx];
        }

        int w = tid >> 5, lane = tid & 31;
        int rowb = (b - MD_BLKS) * 8 + w;

#pragma unroll
        for (int jj = 0; jj < 2; jj++) {
            int j = lane + jj * 32;
            ce[w][j] = fmaxf(z  [(size_t)rowb * DOU + j], 0.f);
            ca[w][j] = fmaxf(za [(size_t)rowb * DOU + j], 0.f);
            cs[w][j] = fmaxf(zsv[(size_t)rowb * DOU + j], 0.f);
        }
        __syncthreads();

        float r1 = 0.f, r2 = 0.f;
#pragma unroll
        for (int dd = 0; dd < 2; dd++) {
            int d = lane + dd * 32;
            float s1 = 0.f, s2 = 0.f;
#pragma unroll
            for (int k = 0; k < 64; k++) {
                float wv = Ws[d * 65 + k];
                s1 = fmaf(wv, ce[w][k], s1);
                s2 = fmaf(wv, ca[w][k], s2);
            }
            r1 = fmaf(ca[w][d], s1, r1);
            r2 = fmaf(cs[w][d], s2, r2);
        }
#pragma unroll
        for (int off = 16; off; off >>= 1) {
            r1 += __shfl_down_sync(0xffffffffu, r1, off);
            r2 += __shfl_down_sync(0xffffffffu, r2, off);
        }
        if (lane == 0) {
            float bv = bptr[0];
            ret[rowb]  = r1 + bv;
            reta[rowb] = r2 + bv;
        }
    }
}

// ---------------------------------------------------------------------------
extern "C" void kernel_launch(void* const* d_in, const int* in_sizes, int n_in,
                              void* d_out, int out_size) {
    const float* feat   = (const float*)d_in[0];
    const float* feat_a = (const float*)d_in[1];
    const int*   row    = (const int*)  d_in[2];
    const int*   col    = (const int*)  d_in[3];
    const float* vals   = (const float*)d_in[4];
    const int*   row_a  = (const int*)  d_in[5];
    const int*   col_a  = (const int*)  d_in[6];
    const float* vals_a = (const float*)d_in[7];
    const float* W1     = (const float*)d_in[8];
    const float* W2     = (const float*)d_in[9];
    const float* discW  = (const float*)d_in[10];
    const float* discB  = (const float*)d_in[11];

    float* out = (float*)d_out;
    float* z_out    = out + OFF_HIDEN;
    float* h_out    = out + OFF_H;
    float* ret_out  = out + OFF_RET;
    float* reta_out = out + OFF_RETA;
    float* mean_out = out + OFF_MEAN;
    float* disp_out = out + OFF_DISP;

    float *p_z0, *p_za0, *p_zaacc, *p_zsacc, *p_t;
    cudaGetSymbolAddress((void**)&p_z0,    g_z0);
    cudaGetSymbolAddress((void**)&p_za0,   g_za0);
    cudaGetSymbolAddress((void**)&p_zaacc, g_zaacc);
    cudaGetSymbolAddress((void**)&p_zsacc, g_zsacc);
    cudaGetSymbolAddress((void**)&p_t,     g_t);

    // 1. z0/za0 GEMMs + zero accumulators (independent, one launch)
    k_phase1<<<2 * GEMM_BLKS + ZERO_BLKS, 128>>>(
        feat, feat_a, W1, p_z0, p_za0,
        (float4*)z_out, (float4*)p_zaacc, (float4*)p_zsacc, (float4*)p_t);

    // 2. mean/disp GEMM || spmm_dual(A: z0->z, za0->zaacc) || spmm(A_a: za0->zsacc)
    k_phase2<<<MD_BLKS + 2 * SP_BLKS, 256>>>(
        row, col, vals, row_a, col_a, vals_a,
        p_z0, p_za0, z_out, p_zaacc, p_zsacc,
        W2, mean_out, disp_out);

    // 3. t = A z
    k_phase3<<<SP_BLKS, 256>>>(row, col, vals, z_out, p_t);

    // 4. h = t@W2 || bilinear discriminators
    k_phase4<<<MD_BLKS + BI_BLKS, 256>>>(
        p_t, W2, h_out,
        z_out, p_zaacc, p_zsacc, discW, discB, ret_out, reta_out);
}

// round 8
// speedup vs baseline: 1.2580x; 1.2580x over previous
#include <cuda_runtime.h>
#include <math.h>

#define NN   20000
#define DIN  1024
#define DOU  64
#define NE   320000
#define SZ   (NN*DOU)

// Output layout (flattened tuple, float32):
//   hiden_emb [N,64], h [N,1024], ret [N,1], ret_a [N,1], mean [N,1024], disp [N,1024]
#define OFF_HIDEN 0
#define OFF_H     ((size_t)SZ)
#define OFF_RET   (OFF_H + (size_t)NN*DIN)
#define OFF_RETA  (OFF_RET + NN)
#define OFF_MEAN  (OFF_RETA + NN)
#define OFF_DISP  (OFF_MEAN + (size_t)NN*DIN)

// Scratch
__device__ float g_z0[SZ];
__device__ float g_za0[SZ];
__device__ float g_zaacc[SZ];
__device__ float g_zsacc[SZ];
__device__ float g_t[SZ];

// ---------------------------------------------------------------------------
// f32x2 packed-FMA helpers
// ---------------------------------------------------------------------------
__device__ __forceinline__ void fma2(unsigned long long& d,
                                     unsigned long long a, unsigned long long b) {
    asm("fma.rn.f32x2 %0, %1, %2, %0;" : "+l"(d) : "l"(a), "l"(b));
}
__device__ __forceinline__ unsigned long long pack2(float x, float y) {
    unsigned long long r;
    asm("mov.b64 %0, {%1, %2};" : "=l"(r) : "f"(x), "f"(y));
    return r;
}
__device__ __forceinline__ void unpack2(unsigned long long v, float& lo, float& hi) {
    asm("mov.b64 {%0, %1}, %2;" : "=f"(lo), "=f"(hi) : "l"(v));
}
__device__ __forceinline__ void red4(float* p, float a, float b, float c, float d) {
    asm volatile("red.global.add.v4.f32 [%0], {%1,%2,%3,%4};"
                 :: "l"(p), "f"(a), "f"(b), "f"(c), "f"(d) : "memory");
}

// ---------------------------------------------------------------------------
// Input GEMM body: C[64-row tile, 64] = A[.,1024] @ B[1024,64]
// ---------------------------------------------------------------------------
__device__ __forceinline__ void gemm64_body(const float* __restrict__ A,
                                            const float* __restrict__ B,
                                            float* __restrict__ C, int bx) {
    __shared__ float As[32 * 64];   // [k][row]
    __shared__ float Bs[32 * 64];   // [k][col]

    int tid = threadIdx.x;
    int rowBase = bx * 64;
    int tx = tid & 15;
    int ty = tid >> 4;

    unsigned long long acc[4][4];
#pragma unroll
    for (int i = 0; i < 4; i++)
#pragma unroll
        for (int j = 0; j < 4; j++) acc[i][j] = 0ull;

    int ar = tid >> 1;
    int ak = (tid & 1) * 16;
    bool aval = (rowBase + ar) < NN;
    const float* arow = A + (size_t)(rowBase + ar) * DIN + ak;

    for (int k0 = 0; k0 < DIN; k0 += 32) {
#pragma unroll
        for (int j = 0; j < 4; j++) {
            float4 v = aval ? *(const float4*)(arow + k0 + 4 * j)
                            : make_float4(0.f, 0.f, 0.f, 0.f);
            int kb = ak + 4 * j;
            As[(kb + 0) * 64 + ar] = v.x;
            As[(kb + 1) * 64 + ar] = v.y;
            As[(kb + 2) * 64 + ar] = v.z;
            As[(kb + 3) * 64 + ar] = v.w;
        }
        const float4* bsrc = (const float4*)(B + (size_t)k0 * DOU);
#pragma unroll
        for (int j = 0; j < 4; j++)
            ((float4*)Bs)[tid + 128 * j] = bsrc[tid + 128 * j];

        __syncthreads();

#pragma unroll 8
        for (int kk = 0; kk < 32; kk++) {
            const ulonglong2* ap = (const ulonglong2*)&As[kk * 64 + ty * 8];
            ulonglong2 aA = ap[0];
            ulonglong2 aB = ap[1];
            float4 bv = *(const float4*)&Bs[kk * 64 + tx * 4];
            unsigned long long b0 = pack2(bv.x, bv.x);
            unsigned long long b1 = pack2(bv.y, bv.y);
            unsigned long long b2 = pack2(bv.z, bv.z);
            unsigned long long b3 = pack2(bv.w, bv.w);
            fma2(acc[0][0], aA.x, b0); fma2(acc[0][1], aA.x, b1);
            fma2(acc[0][2], aA.x, b2); fma2(acc[0][3], aA.x, b3);
            fma2(acc[1][0], aA.y, b0); fma2(acc[1][1], aA.y, b1);
            fma2(acc[1][2], aA.y, b2); fma2(acc[1][3], aA.y, b3);
            fma2(acc[2][0], aB.x, b0); fma2(acc[2][1], aB.x, b1);
            fma2(acc[2][2], aB.x, b2); fma2(acc[2][3], aB.x, b3);
            fma2(acc[3][0], aB.y, b0); fma2(acc[3][1], aB.y, b1);
            fma2(acc[3][2], aB.y, b2); fma2(acc[3][3], aB.y, b3);
        }
        __syncthreads();
    }

#pragma unroll
    for (int rp = 0; rp < 4; rp++) {
        float l0, h0, l1, h1, l2, h2, l3, h3;
        unpack2(acc[rp][0], l0, h0);
        unpack2(acc[rp][1], l1, h1);
        unpack2(acc[rp][2], l2, h2);
        unpack2(acc[rp][3], l3, h3);
        int r0 = rowBase + ty * 8 + rp * 2;
        if (r0 < NN)
            *(float4*)&C[(size_t)r0 * DOU + tx * 4] = make_float4(l0, l1, l2, l3);
        if (r0 + 1 < NN)
            *(float4*)&C[(size_t)(r0 + 1) * DOU + tx * 4] = make_float4(h0, h1, h2, h3);
    }
}

#define GEMM_BLKS 313   // ceil(20000/64)
#define ZERO_BLKS 256

// Phase 1: z0 = feat@W1 ; za0 = feat_a@W1 ; zero the 4 accumulators
__global__ __launch_bounds__(128) void k_phase1(
        const float* __restrict__ feat, const float* __restrict__ feat_a,
        const float* __restrict__ W1,
        float* __restrict__ z0, float* __restrict__ za0,
        float4* __restrict__ zout, float4* __restrict__ zaacc,
        float4* __restrict__ zsacc, float4* __restrict__ t) {
    int b = blockIdx.x;
    if (b < GEMM_BLKS) {
        gemm64_body(feat, W1, z0, b);
    } else if (b < 2 * GEMM_BLKS) {
        gemm64_body(feat_a, W1, za0, b - GEMM_BLKS);
    } else {
        int i = (b - 2 * GEMM_BLKS) * 128 + threadIdx.x;
        int stride = ZERO_BLKS * 128;
        float4 zv = make_float4(0.f, 0.f, 0.f, 0.f);
        for (int j = i; j < SZ / 4; j += stride) {
            zout[j] = zv; zaacc[j] = zv; zsacc[j] = zv; t[j] = zv;
        }
    }
}

// ---------------------------------------------------------------------------
// SpMM bodies (16 threads/edge, red.global.add.v4)
// ---------------------------------------------------------------------------
__device__ __forceinline__ void spmm_dual_body(unsigned idx,
        const int* __restrict__ row, const int* __restrict__ col,
        const float* __restrict__ vals,
        const float* __restrict__ x1, float* y1,
        const float* __restrict__ x2, float* y2) {
    unsigned e = idx >> 4;
    if (e >= NE) return;
    int lane4 = (idx & 15) << 2;
    int r = __ldg(&row[e]), c = __ldg(&col[e]);
    float v = __ldg(&vals[e]);

    const float4 a = __ldg((const float4*)&x1[(size_t)c * DOU + lane4]);
    red4(&y1[(size_t)r * DOU + lane4], v * a.x, v * a.y, v * a.z, v * a.w);

    const float4 bb = __ldg((const float4*)&x2[(size_t)c * DOU + lane4]);
    red4(&y2[(size_t)r * DOU + lane4], v * bb.x, v * bb.y, v * bb.z, v * bb.w);
}

__device__ __forceinline__ void spmm_single_body(unsigned idx,
        const int* __restrict__ row, const int* __restrict__ col,
        const float* __restrict__ vals,
        const float* __restrict__ x1, float* y1) {
    unsigned e = idx >> 4;
    if (e >= NE) return;
    int lane4 = (idx & 15) << 2;
    int r = __ldg(&row[e]), c = __ldg(&col[e]);
    float v = __ldg(&vals[e]);

    const float4 a = __ldg((const float4*)&x1[(size_t)c * DOU + lane4]);
    red4(&y1[(size_t)r * DOU + lane4], v * a.x, v * a.y, v * a.z, v * a.w);
}

#define SP_BLKS 20000   // NE*16/256

// Phase 2: z = A z0, zaacc = A za0  ||  zsacc = A_a za0  (all atomic-bound)
__global__ __launch_bounds__(256) void k_phase2(
        const int* __restrict__ row,  const int* __restrict__ col,
        const float* __restrict__ vals,
        const int* __restrict__ row_a, const int* __restrict__ col_a,
        const float* __restrict__ vals_a,
        const float* __restrict__ z0, const float* __restrict__ za0,
        float* __restrict__ zout, float* __restrict__ zaacc,
        float* __restrict__ zsacc) {
    int b = blockIdx.x;
    if (b < SP_BLKS) {
        unsigned idx = (unsigned)b * 256u + threadIdx.x;
        spmm_dual_body(idx, row, col, vals, z0, zout, za0, zaacc);
    } else {
        unsigned idx = (unsigned)(b - SP_BLKS) * 256u + threadIdx.x;
        spmm_single_body(idx, row_a, col_a, vals_a, za0, zsacc);
    }
}

#define BI_BLKS 2500   // NN/8

// Phase 3: t = A z  ||  bilinear discriminators
__global__ __launch_bounds__(256) void k_phase3(
        const int* __restrict__ row, const int* __restrict__ col,
        const float* __restrict__ vals,
        const float* __restrict__ z, float* __restrict__ t,
        const float* __restrict__ za, const float* __restrict__ zsv,
        const float* __restrict__ W, const float* __restrict__ bptr,
        float* __restrict__ ret, float* __restrict__ reta) {
    int b = blockIdx.x;
    if (b < SP_BLKS) {
        unsigned idx = (unsigned)b * 256u + threadIdx.x;
        spmm_single_body(idx, row, col, vals, z, t);
    } else {
        __shared__ float Ws[64 * 65];
        __shared__ float ce[8][64], ca[8][64], cs[8][64];

        int tid = threadIdx.x;
        for (int idx = tid; idx < 4096; idx += 256) {
            int d = idx >> 6, k = idx & 63;
            Ws[d * 65 + k] = W[idx];
        }

        int w = tid >> 5, lane = tid & 31;
        int rowb = (b - SP_BLKS) * 8 + w;

#pragma unroll
        for (int jj = 0; jj < 2; jj++) {
            int j = lane + jj * 32;
            ce[w][j] = fmaxf(z  [(size_t)rowb * DOU + j], 0.f);
            ca[w][j] = fmaxf(za [(size_t)rowb * DOU + j], 0.f);
            cs[w][j] = fmaxf(zsv[(size_t)rowb * DOU + j], 0.f);
        }
        __syncthreads();

        float r1 = 0.f, r2 = 0.f;
#pragma unroll
        for (int dd = 0; dd < 2; dd++) {
            int d = lane + dd * 32;
            float s1 = 0.f, s2 = 0.f;
#pragma unroll
            for (int k = 0; k < 64; k++) {
                float wv = Ws[d * 65 + k];
                s1 = fmaf(wv, ce[w][k], s1);
                s2 = fmaf(wv, ca[w][k], s2);
            }
            r1 = fmaf(ca[w][d], s1, r1);
            r2 = fmaf(cs[w][d], s2, r2);
        }
#pragma unroll
        for (int off = 16; off; off >>= 1) {
            r1 += __shfl_down_sync(0xffffffffu, r1, off);
            r2 += __shfl_down_sync(0xffffffffu, r2, off);
        }
        if (lane == 0) {
            float bv = bptr[0];
            ret[rowb]  = r1 + bv;
            reta[rowb] = r2 + bv;
        }
    }
}

// ---------------------------------------------------------------------------
// Phase 4: combined wide GEMM. Block computes rows[rb,rb+64) x cols[cb,cb+64)
// of BOTH h = T@W2 and zinb = Z0@W2 (-> mean/disp), sharing the W2 smem tile.
// K=64 loaded once, no k-tiling. 256 threads, 4x4 micro-tile per matrix,
// f32x2 row-pair packing. FFMA2:LDS = 16:3.
// ---------------------------------------------------------------------------
#define TS_PAD 68
#define WIDE_SMEM ((2 * 64 * TS_PAD + 64 * 64) * 4)   // 51200 bytes

__global__ __launch_bounds__(256) void k_wide(
        const float* __restrict__ T, const float* __restrict__ Z0,
        const float* __restrict__ W2,
        float* __restrict__ hout, float* __restrict__ meanout,
        float* __restrict__ dispout) {
    extern __shared__ float sm[];
    float* Ts  = sm;                       // [64 k][68 pad] rows in low 64
    float* Zs  = sm + 64 * TS_PAD;
    float* W2s = sm + 2 * 64 * TS_PAD;     // [64 k][64 cols]

    int tid = threadIdx.x;
    int colTile = blockIdx.x & 15;         // 16 x 64 = 1024 cols
    int rowTile = blockIdx.x >> 4;         // 313 x 64 rows
    int rb = rowTile * 64;
    int cb = colTile * 64;

    // --- load T and Z0 tiles (k-major, transposed) ---
#pragma unroll
    for (int i = 0; i < 4; i++) {
        int lin = tid + i * 256;           // 0..1023 float4s
        int r = lin >> 4;
        int k4 = (lin & 15) << 2;
        int gr = rb + r;
        float4 tv = make_float4(0.f, 0.f, 0.f, 0.f), zv = tv;
        if (gr < NN) {
            tv = __ldg((const float4*)&T [(size_t)gr * DOU + k4]);
            zv = __ldg((const float4*)&Z0[(size_t)gr * DOU + k4]);
        }
        Ts[(k4 + 0) * TS_PAD + r] = tv.x; Ts[(k4 + 1) * TS_PAD + r] = tv.y;
        Ts[(k4 + 2) * TS_PAD + r] = tv.z; Ts[(k4 + 3) * TS_PAD + r] = tv.w;
        Zs[(k4 + 0) * TS_PAD + r] = zv.x; Zs[(k4 + 1) * TS_PAD + r] = zv.y;
        Zs[(k4 + 2) * TS_PAD + r] = zv.z; Zs[(k4 + 3) * TS_PAD + r] = zv.w;
    }
    // --- load W2 tile [64][64] ---
#pragma unroll
    for (int i = 0; i < 4; i++) {
        int lin = tid + i * 256;           // 0..1023 float4s
        int k = lin >> 4;
        int c4 = (lin & 15) << 2;
        *(float4*)&W2s[k * 64 + c4] =
            __ldg((const float4*)&W2[(size_t)k * DIN + cb + c4]);
    }
    __syncthreads();

    int colg = tid & 15;    // 16 groups x 4 cols
    int rowg = tid >> 4;    // 16 groups x 4 rows

    unsigned long long accT[2][4], accZ[2][4];
#pragma unroll
    for (int p = 0; p < 2; p++)
#pragma unroll
        for (int c = 0; c < 4; c++) { accT[p][c] = 0ull; accZ[p][c] = 0ull; }

#pragma unroll 16
    for (int k = 0; k < 64; k++) {
        ulonglong2 tv = *(const ulonglong2*)&Ts[k * TS_PAD + rowg * 4];
        ulonglong2 zv = *(const ulonglong2*)&Zs[k * TS_PAD + rowg * 4];
        float4 wv = *(const float4*)&W2s[k * 64 + colg * 4];
        unsigned long long w0 = pack2(wv.x, wv.x);
        unsigned long long w1 = pack2(wv.y, wv.y);
        unsigned long long w2 = pack2(wv.z, wv.z);
        unsigned long long w3 = pack2(wv.w, wv.w);
        fma2(accT[0][0], tv.x, w0); fma2(accT[0][1], tv.x, w1);
        fma2(accT[0][2], tv.x, w2); fma2(accT[0][3], tv.x, w3);
        fma2(accT[1][0], tv.y, w0); fma2(accT[1][1], tv.y, w1);
        fma2(accT[1][2], tv.y, w2); fma2(accT[1][3], tv.y, w3);
        fma2(accZ[0][0], zv.x, w0); fma2(accZ[0][1], zv.x, w1);
        fma2(accZ[0][2], zv.x, w2); fma2(accZ[0][3], zv.x, w3);
        fma2(accZ[1][0], zv.y, w0); fma2(accZ[1][1], zv.y, w1);
        fma2(accZ[1][2], zv.y, w2); fma2(accZ[1][3], zv.y, w3);
    }

    int c0 = cb + colg * 4;
#pragma unroll
    for (int p = 0; p < 2; p++) {
        int r0 = rb + rowg * 4 + p * 2;
        float tl0, th0, tl1, th1, tl2, th2, tl3, th3;
        unpack2(accT[p][0], tl0, th0); unpack2(accT[p][1], tl1, th1);
        unpack2(accT[p][2], tl2, th2); unpack2(accT[p][3], tl3, th3);
        float zl0, zh0, zl1, zh1, zl2, zh2, zl3, zh3;
        unpack2(accZ[p][0], zl0, zh0); unpack2(accZ[p][1], zl1, zh1);
        unpack2(accZ[p][2], zl2, zh2); unpack2(accZ[p][3], zl3, zh3);

        float hrow[2][4] = {{tl0, tl1, tl2, tl3}, {th0, th1, th2, th3}};
        float zrow[2][4] = {{zl0, zl1, zl2, zl3}, {zh0, zh1, zh2, zh3}};
#pragma unroll
        for (int q = 0; q < 2; q++) {
            int r = r0 + q;
            if (r >= NN) continue;
            size_t o = (size_t)r * DIN + c0;
            __stcs((float4*)&hout[o],
                   make_float4(hrow[q][0], hrow[q][1], hrow[q][2], hrow[q][3]));
            float4 mv, dv;
            float* mp = &mv.x; float* dp = &dv.x;
#pragma unroll
            for (int c = 0; c < 4; c++) {
                float x = zrow[q][c];
                mp[c] = fminf(fmaxf(__expf(x), 1e-5f), 1e6f);
                float sp = fmaxf(x, 0.f) + __logf(1.f + __expf(-fabsf(x)));
                dp[c] = fminf(fmaxf(sp, 1e-4f), 1e4f);
            }
            __stcs((float4*)&meanout[o], mv);
            __stcs((float4*)&dispout[o], dv);
        }
    }
}

// ---------------------------------------------------------------------------
extern "C" void kernel_launch(void* const* d_in, const int* in_sizes, int n_in,
                              void* d_out, int out_size) {
    const float* feat   = (const float*)d_in[0];
    const float* feat_a = (const float*)d_in[1];
    const int*   row    = (const int*)  d_in[2];
    const int*   col    = (const int*)  d_in[3];
    const float* vals   = (const float*)d_in[4];
    const int*   row_a  = (const int*)  d_in[5];
    const int*   col_a  = (const int*)  d_in[6];
    const float* vals_a = (const float*)d_in[7];
    const float* W1     = (const float*)d_in[8];
    const float* W2     = (const float*)d_in[9];
    const float* discW  = (const float*)d_in[10];
    const float* discB  = (const float*)d_in[11];

    float* out = (float*)d_out;
    float* z_out    = out + OFF_HIDEN;
    float* h_out    = out + OFF_H;
    float* ret_out  = out + OFF_RET;
    float* reta_out = out + OFF_RETA;
    float* mean_out = out + OFF_MEAN;
    float* disp_out = out + OFF_DISP;

    float *p_z0, *p_za0, *p_zaacc, *p_zsacc, *p_t;
    cudaGetSymbolAddress((void**)&p_z0,    g_z0);
    cudaGetSymbolAddress((void**)&p_za0,   g_za0);
    cudaGetSymbolAddress((void**)&p_zaacc, g_zaacc);
    cudaGetSymbolAddress((void**)&p_zsacc, g_zsacc);
    cudaGetSymbolAddress((void**)&p_t,     g_t);

    static int smem_set = 0;
    if (!smem_set) {
        cudaFuncSetAttribute(k_wide, cudaFuncAttributeMaxDynamicSharedMemorySize,
                             WIDE_SMEM);
        smem_set = 1;
    }

    // 1. z0/za0 GEMMs + zero accumulators
    k_phase1<<<2 * GEMM_BLKS + ZERO_BLKS, 128>>>(
        feat, feat_a, W1, p_z0, p_za0,
        (float4*)z_out, (float4*)p_zaacc, (float4*)p_zsacc, (float4*)p_t);

    // 2. spmm_dual(A: z0->z, za0->zaacc) || spmm(A_a: za0->zsacc)
    k_phase2<<<2 * SP_BLKS, 256>>>(
        row, col, vals, row_a, col_a, vals_a,
        p_z0, p_za0, z_out, p_zaacc, p_zsacc);

    // 3. t = A z || bilinear discriminators
    k_phase3<<<SP_BLKS + BI_BLKS, 256>>>(
        row, col, vals, z_out, p_t,
        p_zaacc, p_zsacc, discW, discB, ret_out, reta_out);

    // 4. h = t@W2 and mean/disp from z0@W2 (shared W2 tile)
    k_wide<<<313 * 16, 256, WIDE_SMEM>>>(p_t, p_z0, W2,
                                         h_out, mean_out, disp_out);
}

// round 11
// speedup vs baseline: 2.0239x; 1.6089x over previous
#include <cuda_runtime.h>
#include <math.h>
#include <stdint.h>

#define NN   20000
#define DIN  1024
#define DOU  64
#define NE   320000
#define SZ   (NN*DOU)

// Output layout (flattened tuple, float32):
//   hiden_emb [N,64], h [N,1024], ret [N,1], ret_a [N,1], mean [N,1024], disp [N,1024]
#define OFF_HIDEN 0
#define OFF_H     ((size_t)SZ)
#define OFF_RET   (OFF_H + (size_t)NN*DIN)
#define OFF_RETA  (OFF_RET + NN)
#define OFF_MEAN  (OFF_RETA + NN)
#define OFF_DISP  (OFF_MEAN + (size_t)NN*DIN)

// Scratch
__device__ float g_z0[SZ];
__device__ float g_za0[SZ];
__device__ float g_zaacc[SZ];
__device__ float g_zsacc[SZ];
__device__ float g_t[SZ];

// ---------------------------------------------------------------------------
// helpers
// ---------------------------------------------------------------------------
__device__ __forceinline__ void red4(float* p, float a, float b, float c, float d) {
    asm volatile("red.global.add.v4.f32 [%0], {%1,%2,%3,%4};"
                 :: "l"(p), "f"(a), "f"(b), "f"(c), "f"(d) : "memory");
}

// round-to-nearest tf32 (returned as fp32 bit pattern)
__device__ __forceinline__ float tf32r(float x) {
    uint32_t u;
    asm("cvt.rna.tf32.f32 %0, %1;" : "=r"(u) : "f"(x));
    return __uint_as_float(u);
}
__device__ __forceinline__ float4 tf32r4(float4 v) {
    return make_float4(tf32r(v.x), tf32r(v.y), tf32r(v.z), tf32r(v.w));
}

// m16n8k8 tf32 MMA (row.col), D += A*B
__device__ __forceinline__ void mma_tf32(float* d, uint32_t a0, uint32_t a1,
                                         uint32_t a2, uint32_t a3,
                                         uint32_t b0, uint32_t b1) {
    asm("mma.sync.aligned.m16n8k8.row.col.f32.tf32.tf32.f32 "
        "{%0,%1,%2,%3}, {%4,%5,%6,%7}, {%8,%9}, {%0,%1,%2,%3};"
        : "+f"(d[0]), "+f"(d[1]), "+f"(d[2]), "+f"(d[3])
        : "r"(a0), "r"(a1), "r"(a2), "r"(a3), "r"(b0), "r"(b1));
}

#define XPAD 68   // row stride of X smem tiles [64 rows][64 k]
#define WPAD 72   // row stride of W smem tiles [64 k][64 n]

// Warp computes a 32x32 output tile over a 64-deep k reduction.
// Xs: [64][XPAD] row-major (rows x k), Ws: [64][WPAD] (k x n).
// ro/co: 0 or 32. acc[2 m-frags][4 n-frags][4].
__device__ __forceinline__ void warp_mma_64k(const float* __restrict__ Xs,
                                             const float* __restrict__ Ws,
                                             int ro, int co, int lane,
                                             float acc[2][4][4]) {
    int gid = lane >> 2, tig = lane & 3;
#pragma unroll
    for (int kk = 0; kk < 64; kk += 8) {
        uint32_t a[2][4];
#pragma unroll
        for (int mi = 0; mi < 2; mi++) {
            const float* base = Xs + (ro + mi * 16 + gid) * XPAD + kk + tig;
            a[mi][0] = __float_as_uint(base[0]);
            a[mi][1] = __float_as_uint(base[8 * XPAD]);
            a[mi][2] = __float_as_uint(base[4]);
            a[mi][3] = __float_as_uint(base[8 * XPAD + 4]);
        }
#pragma unroll
        for (int ni = 0; ni < 4; ni++) {
            const float* wb = Ws + (kk + tig) * WPAD + co + ni * 8 + gid;
            uint32_t b0 = __float_as_uint(wb[0]);
            uint32_t b1 = __float_as_uint(wb[4 * WPAD]);
#pragma unroll
            for (int mi = 0; mi < 2; mi++)
                mma_tf32(acc[mi][ni], a[mi][0], a[mi][1], a[mi][2], a[mi][3],
                         b0, b1);
        }
    }
}

// ---------------------------------------------------------------------------
// Input GEMM (tf32): C[64-row tile, 64] = A[.,1024] @ B[1024,64]
// 128 threads = 4 warps, warp tile 32x32, k-tiles of 64.
// ---------------------------------------------------------------------------
__device__ __forceinline__ void gemm_in_tf32(const float* __restrict__ A,
                                             const float* __restrict__ B,
                                             float* __restrict__ C, int bx) {
    __shared__ float As[64 * XPAD];
    __shared__ float Bs[64 * WPAD];

    int tid = threadIdx.x;
    int w = tid >> 5, lane = tid & 31;
    int wr = w & 1, wc = w >> 1;
    int rb = bx * 64;

    float acc[2][4][4];
#pragma unroll
    for (int mi = 0; mi < 2; mi++)
#pragma unroll
        for (int ni = 0; ni < 4; ni++)
#pragma unroll
            for (int q = 0; q < 4; q++) acc[mi][ni][q] = 0.f;

    for (int k0 = 0; k0 < DIN; k0 += 64) {
        // stage A tile [64 rows][64 k] (1024 float4 chunks / 128 thr = 8)
#pragma unroll
        for (int i = 0; i < 8; i++) {
            int chunk = tid + 128 * i;
            int r = chunk >> 4, k4 = (chunk & 15) << 2;
            int gr = rb + r;
            float4 v = (gr < NN)
                ? __ldg((const float4*)&A[(size_t)gr * DIN + k0 + k4])
                : make_float4(0.f, 0.f, 0.f, 0.f);
            *(float4*)&As[r * XPAD + k4] = tf32r4(v);
        }
        // stage B slab [64 k][64 n]
#pragma unroll
        for (int i = 0; i < 8; i++) {
            int chunk = tid + 128 * i;
            int k = chunk >> 4, n4 = (chunk & 15) << 2;
            float4 v = __ldg((const float4*)&B[(size_t)(k0 + k) * DOU + n4]);
            *(float4*)&Bs[k * WPAD + n4] = tf32r4(v);
        }
        __syncthreads();
        warp_mma_64k(As, Bs, wr * 32, wc * 32, lane, acc);
        __syncthreads();
    }

    int gid = lane >> 2, tig = lane & 3;
#pragma unroll
    for (int mi = 0; mi < 2; mi++) {
#pragma unroll
        for (int ni = 0; ni < 4; ni++) {
            int r0 = rb + wr * 32 + mi * 16 + gid;
            int c  = wc * 32 + ni * 8 + tig * 2;
            if (r0 < NN)
                *(float2*)&C[(size_t)r0 * DOU + c] =
                    make_float2(acc[mi][ni][0], acc[mi][ni][1]);
            if (r0 + 8 < NN)
                *(float2*)&C[(size_t)(r0 + 8) * DOU + c] =
                    make_float2(acc[mi][ni][2], acc[mi][ni][3]);
        }
    }
}

#define GEMM_BLKS 313   // ceil(20000/64)
#define ZERO_BLKS 256

// Phase 1: z0 = feat@W1 ; za0 = feat_a@W1 ; zero the 4 accumulators
__global__ __launch_bounds__(128) void k_phase1(
        const float* __restrict__ feat, const float* __restrict__ feat_a,
        const float* __restrict__ W1,
        float* __restrict__ z0, float* __restrict__ za0,
        float4* __restrict__ zout, float4* __restrict__ zaacc,
        float4* __restrict__ zsacc, float4* __restrict__ t) {
    int b = blockIdx.x;
    if (b < GEMM_BLKS) {
        gemm_in_tf32(feat, W1, z0, b);
    } else if (b < 2 * GEMM_BLKS) {
        gemm_in_tf32(feat_a, W1, za0, b - GEMM_BLKS);
    } else {
        int i = (b - 2 * GEMM_BLKS) * 128 + threadIdx.x;
        int stride = ZERO_BLKS * 128;
        float4 zv = make_float4(0.f, 0.f, 0.f, 0.f);
        for (int j = i; j < SZ / 4; j += stride) {
            zout[j] = zv; zaacc[j] = zv; zsacc[j] = zv; t[j] = zv;
        }
    }
}

// ---------------------------------------------------------------------------
// SpMM bodies (16 threads/edge, red.global.add.v4)
// ---------------------------------------------------------------------------
__device__ __forceinline__ void spmm_dual_body(unsigned idx,
        const int* __restrict__ row, const int* __restrict__ col,
        const float* __restrict__ vals,
        const float* __restrict__ x1, float* y1,
        const float* __restrict__ x2, float* y2) {
    unsigned e = idx >> 4;
    if (e >= NE) return;
    int lane4 = (idx & 15) << 2;
    int r = __ldg(&row[e]), c = __ldg(&col[e]);
    float v = __ldg(&vals[e]);

    const float4 a = __ldg((const float4*)&x1[(size_t)c * DOU + lane4]);
    red4(&y1[(size_t)r * DOU + lane4], v * a.x, v * a.y, v * a.z, v * a.w);

    const float4 bb = __ldg((const float4*)&x2[(size_t)c * DOU + lane4]);
    red4(&y2[(size_t)r * DOU + lane4], v * bb.x, v * bb.y, v * bb.z, v * bb.w);
}

__device__ __forceinline__ void spmm_single_body(unsigned idx,
        const int* __restrict__ row, const int* __restrict__ col,
        const float* __restrict__ vals,
        const float* __restrict__ x1, float* y1) {
    unsigned e = idx >> 4;
    if (e >= NE) return;
    int lane4 = (idx & 15) << 2;
    int r = __ldg(&row[e]), c = __ldg(&col[e]);
    float v = __ldg(&vals[e]);

    const float4 a = __ldg((const float4*)&x1[(size_t)c * DOU + lane4]);
    red4(&y1[(size_t)r * DOU + lane4], v * a.x, v * a.y, v * a.z, v * a.w);
}

#define SP_BLKS 20000   // NE*16/256

// Phase 2: z = A z0, zaacc = A za0  ||  zsacc = A_a za0
__global__ __launch_bounds__(256) void k_phase2(
        const int* __restrict__ row,  const int* __restrict__ col,
        const float* __restrict__ vals,
        const int* __restrict__ row_a, const int* __restrict__ col_a,
        const float* __restrict__ vals_a,
        const float* __restrict__ z0, const float* __restrict__ za0,
        float* __restrict__ zout, float* __restrict__ zaacc,
        float* __restrict__ zsacc) {
    int b = blockIdx.x;
    if (b < SP_BLKS) {
        unsigned idx = (unsigned)b * 256u + threadIdx.x;
        spmm_dual_body(idx, row, col, vals, z0, zout, za0, zaacc);
    } else {
        unsigned idx = (unsigned)(b - SP_BLKS) * 256u + threadIdx.x;
        spmm_single_body(idx, row_a, col_a, vals_a, za0, zsacc);
    }
}

#define BI_BLKS 2500   // NN/8

// Phase 3: t = A z  ||  bilinear discriminators
__global__ __launch_bounds__(256) void k_phase3(
        const int* __restrict__ row, const int* __restrict__ col,
        const float* __restrict__ vals,
        const float* __restrict__ z, float* __restrict__ t,
        const float* __restrict__ za, const float* __restrict__ zsv,
        const float* __restrict__ W, const float* __restrict__ bptr,
        float* __restrict__ ret, float* __restrict__ reta) {
    int b = blockIdx.x;
    if (b < SP_BLKS) {
        unsigned idx = (unsigned)b * 256u + threadIdx.x;
        spmm_single_body(idx, row, col, vals, z, t);
    } else {
        __shared__ float Ws[64 * 65];
        __shared__ float ce[8][64], ca[8][64], cs[8][64];

        int tid = threadIdx.x;
        for (int idx = tid; idx < 4096; idx += 256) {
            int d = idx >> 6, k = idx & 63;
            Ws[d * 65 + k] = W[idx];
        }

        int w = tid >> 5, lane = tid & 31;
        int rowb = (b - SP_BLKS) * 8 + w;

#pragma unroll
        for (int jj = 0; jj < 2; jj++) {
            int j = lane + jj * 32;
            ce[w][j] = fmaxf(z  [(size_t)rowb * DOU + j], 0.f);
            ca[w][j] = fmaxf(za [(size_t)rowb * DOU + j], 0.f);
            cs[w][j] = fmaxf(zsv[(size_t)rowb * DOU + j], 0.f);
        }
        __syncthreads();

        float r1 = 0.f, r2 = 0.f;
#pragma unroll
        for (int dd = 0; dd < 2; dd++) {
            int d = lane + dd * 32;
            float s1 = 0.f, s2 = 0.f;
#pragma unroll
            for (int k = 0; k < 64; k++) {
                float wv = Ws[d * 65 + k];
                s1 = fmaf(wv, ce[w][k], s1);
                s2 = fmaf(wv, ca[w][k], s2);
            }
            r1 = fmaf(ca[w][d], s1, r1);
            r2 = fmaf(cs[w][d], s2, r2);
        }
#pragma unroll
        for (int off = 16; off; off >>= 1) {
            r1 += __shfl_down_sync(0xffffffffu, r1, off);
            r2 += __shfl_down_sync(0xffffffffu, r2, off);
        }
        if (lane == 0) {
            float bv = bptr[0];
            ret[rowb]  = r1 + bv;
            reta[rowb] = r2 + bv;
        }
    }
}

// ---------------------------------------------------------------------------
// Phase 4 (tf32 tensor): block computes rows[rb,rb+64) x cols[cb,cb+64) of
// BOTH h = T@W2 and zinb = Z0@W2 (-> mean/disp), sharing the W2 smem tile.
// 256 threads = 8 warps: mat(2) x wr(2) x wc(2), warp tile 32x32, K=64.
// ---------------------------------------------------------------------------
#define WIDE_SMEM ((2 * 64 * XPAD + 64 * WPAD) * 4)   // 53248 bytes

__global__ __launch_bounds__(256) void k_wide(
        const float* __restrict__ T, const float* __restrict__ Z0,
        const float* __restrict__ W2,
        float* __restrict__ hout, float* __restrict__ meanout,
        float* __restrict__ dispout) {
    extern __shared__ float sm[];
    float* Ts = sm;
    float* Zs = sm + 64 * XPAD;
    float* Ws = sm + 2 * 64 * XPAD;

    int tid = threadIdx.x;
    int colTile = blockIdx.x & 15;
    int rowTile = blockIdx.x >> 4;
    int rb = rowTile * 64;
    int cb = colTile * 64;

    // stage T/Z tiles [64 rows][64 k]
#pragma unroll
    for (int i = 0; i < 4; i++) {
        int chunk = tid + 256 * i;
        int r = chunk >> 4, k4 = (chunk & 15) << 2;
        int gr = rb + r;
        float4 tv = make_float4(0.f, 0.f, 0.f, 0.f), zv = tv;
        if (gr < NN) {
            tv = __ldg((const float4*)&T [(size_t)gr * DOU + k4]);
            zv = __ldg((const float4*)&Z0[(size_t)gr * DOU + k4]);
        }
        *(float4*)&Ts[r * XPAD + k4] = tf32r4(tv);
        *(float4*)&Zs[r * XPAD + k4] = tf32r4(zv);
    }
    // stage W2 tile [64 k][64 n]
#pragma unroll
    for (int i = 0; i < 4; i++) {
        int chunk = tid + 256 * i;
        int k = chunk >> 4, n4 = (chunk & 15) << 2;
        float4 v = __ldg((const float4*)&W2[(size_t)k * DIN + cb + n4]);
        *(float4*)&Ws[k * WPAD + n4] = tf32r4(v);
    }
    __syncthreads();

    int w = tid >> 5, lane = tid & 31;
    int mat = w & 1, wr = (w >> 1) & 1, wc = w >> 2;
    const float* Xs = mat ? Zs : Ts;

    float acc[2][4][4];
#pragma unroll
    for (int mi = 0; mi < 2; mi++)
#pragma unroll
        for (int ni = 0; ni < 4; ni++)
#pragma unroll
            for (int q = 0; q < 4; q++) acc[mi][ni][q] = 0.f;

    warp_mma_64k(Xs, Ws, wr * 32, wc * 32, lane, acc);

    int gid = lane >> 2, tig = lane & 3;
#pragma unroll
    for (int mi = 0; mi < 2; mi++) {
#pragma unroll
        for (int ni = 0; ni < 4; ni++) {
            int r0 = rb + wr * 32 + mi * 16 + gid;
            int r1 = r0 + 8;
            int c  = cb + wc * 32 + ni * 8 + tig * 2;
            if (mat == 0) {
                if (r0 < NN)
                    __stcs((float2*)&hout[(size_t)r0 * DIN + c],
                           make_float2(acc[mi][ni][0], acc[mi][ni][1]));
                if (r1 < NN)
                    __stcs((float2*)&hout[(size_t)r1 * DIN + c],
                           make_float2(acc[mi][ni][2], acc[mi][ni][3]));
            } else {
                float x0 = acc[mi][ni][0], x1 = acc[mi][ni][1];
                float x2 = acc[mi][ni][2], x3 = acc[mi][ni][3];
                if (r0 < NN) {
                    size_t o = (size_t)r0 * DIN + c;
                    __stcs((float2*)&meanout[o],
                        make_float2(fminf(fmaxf(__expf(x0), 1e-5f), 1e6f),
                                    fminf(fmaxf(__expf(x1), 1e-5f), 1e6f)));
                    float s0 = fmaxf(x0, 0.f) + __logf(1.f + __expf(-fabsf(x0)));
                    float s1 = fmaxf(x1, 0.f) + __logf(1.f + __expf(-fabsf(x1)));
                    __stcs((float2*)&dispout[o],
                        make_float2(fminf(fmaxf(s0, 1e-4f), 1e4f),
                                    fminf(fmaxf(s1, 1e-4f), 1e4f)));
                }
                if (r1 < NN) {
                    size_t o = (size_t)r1 * DIN + c;
                    __stcs((float2*)&meanout[o],
                        make_float2(fminf(fmaxf(__expf(x2), 1e-5f), 1e6f),
                                    fminf(fmaxf(__expf(x3), 1e-5f), 1e6f)));
                    float s2 = fmaxf(x2, 0.f) + __logf(1.f + __expf(-fabsf(x2)));
                    float s3 = fmaxf(x3, 0.f) + __logf(1.f + __expf(-fabsf(x3)));
                    __stcs((float2*)&dispout[o],
                        make_float2(fminf(fmaxf(s2, 1e-4f), 1e4f),
                                    fminf(fmaxf(s3, 1e-4f), 1e4f)));
                }
            }
        }
    }
}

// ---------------------------------------------------------------------------
extern "C" void kernel_launch(void* const* d_in, const int* in_sizes, int n_in,
                              void* d_out, int out_size) {
    const float* feat   = (const float*)d_in[0];
    const float* feat_a = (const float*)d_in[1];
    const int*   row    = (const int*)  d_in[2];
    const int*   col    = (const int*)  d_in[3];
    const float* vals   = (const float*)d_in[4];
    const int*   row_a  = (const int*)  d_in[5];
    const int*   col_a  = (const int*)  d_in[6];
    const float* vals_a = (const float*)d_in[7];
    const float* W1     = (const float*)d_in[8];
    const float* W2     = (const float*)d_in[9];
    const float* discW  = (const float*)d_in[10];
    const float* discB  = (const float*)d_in[11];

    float* out = (float*)d_out;
    float* z_out    = out + OFF_HIDEN;
    float* h_out    = out + OFF_H;
    float* ret_out  = out + OFF_RET;
    float* reta_out = out + OFF_RETA;
    float* mean_out = out + OFF_MEAN;
    float* disp_out = out + OFF_DISP;

    float *p_z0, *p_za0, *p_zaacc, *p_zsacc, *p_t;
    cudaGetSymbolAddress((void**)&p_z0,    g_z0);
    cudaGetSymbolAddress((void**)&p_za0,   g_za0);
    cudaGetSymbolAddress((void**)&p_zaacc, g_zaacc);
    cudaGetSymbolAddress((void**)&p_zsacc, g_zsacc);
    cudaGetSymbolAddress((void**)&p_t,     g_t);

    static int smem_set = 0;
    if (!smem_set) {
        cudaFuncSetAttribute(k_wide, cudaFuncAttributeMaxDynamicSharedMemorySize,
                             WIDE_SMEM);
        smem_set = 1;
    }

    // 1. z0/za0 GEMMs (tf32 tensor) + zero accumulators
    k_phase1<<<2 * GEMM_BLKS + ZERO_BLKS, 128>>>(
        feat, feat_a, W1, p_z0, p_za0,
        (float4*)z_out, (float4*)p_zaacc, (float4*)p_zsacc, (float4*)p_t);

    // 2. spmm_dual(A: z0->z, za0->zaacc) || spmm(A_a: za0->zsacc)
    k_phase2<<<2 * SP_BLKS, 256>>>(
        row, col, vals, row_a, col_a, vals_a,
        p_z0, p_za0, z_out, p_zaacc, p_zsacc);

    // 3. t = A z || bilinear discriminators
    k_phase3<<<SP_BLKS + BI_BLKS, 256>>>(
        row, col, vals, z_out, p_t,
        p_zaacc, p_zsacc, discW, discB, ret_out, reta_out);

    // 4. h = t@W2 and mean/disp from z0@W2 (tf32 tensor, shared W2 tile)
    k_wide<<<313 * 16, 256, WIDE_SMEM>>>(p_t, p_z0, W2,
                                         h_out, mean_out, disp_out);
}

// round 12
// speedup vs baseline: 2.0618x; 1.0187x over previous
#include <cuda_runtime.h>
#include <math.h>
#include <stdint.h>

#define NN   20000
#define DIN  1024
#define DOU  64
#define NE   320000
#define SZ   (NN*DOU)

// Output layout (flattened tuple, float32):
//   hiden_emb [N,64], h [N,1024], ret [N,1], ret_a [N,1], mean [N,1024], disp [N,1024]
#define OFF_HIDEN 0
#define OFF_H     ((size_t)SZ)
#define OFF_RET   (OFF_H + (size_t)NN*DIN)
#define OFF_RETA  (OFF_RET + NN)
#define OFF_MEAN  (OFF_RETA + NN)
#define OFF_DISP  (OFF_MEAN + (size_t)NN*DIN)

// Scratch
__device__ float g_z0[SZ];
__device__ float g_za0[SZ];
__device__ float g_zaacc[SZ];
__device__ float g_zsacc[SZ];
__device__ float g_t[SZ];

// ---------------------------------------------------------------------------
// helpers
// ---------------------------------------------------------------------------
__device__ __forceinline__ void red4(float* p, float a, float b, float c, float d) {
    asm volatile("red.global.add.v4.f32 [%0], {%1,%2,%3,%4};"
                 :: "l"(p), "f"(a), "f"(b), "f"(c), "f"(d) : "memory");
}

// round-to-nearest tf32 (returned as fp32 bit pattern)
__device__ __forceinline__ float tf32r(float x) {
    uint32_t u;
    asm("cvt.rna.tf32.f32 %0, %1;" : "=r"(u) : "f"(x));
    return __uint_as_float(u);
}
__device__ __forceinline__ float4 tf32r4(float4 v) {
    return make_float4(tf32r(v.x), tf32r(v.y), tf32r(v.z), tf32r(v.w));
}

// m16n8k8 tf32 MMA (row.col), D += A*B
__device__ __forceinline__ void mma_tf32(float* d, uint32_t a0, uint32_t a1,
                                         uint32_t a2, uint32_t a3,
                                         uint32_t b0, uint32_t b1) {
    asm("mma.sync.aligned.m16n8k8.row.col.f32.tf32.tf32.f32 "
        "{%0,%1,%2,%3}, {%4,%5,%6,%7}, {%8,%9}, {%0,%1,%2,%3};"
        : "+f"(d[0]), "+f"(d[1]), "+f"(d[2]), "+f"(d[3])
        : "r"(a0), "r"(a1), "r"(a2), "r"(a3), "r"(b0), "r"(b1));
}

#define XPAD 68   // row stride of X smem tiles [64 rows][64 k]
#define WPAD 72   // row stride of W smem tiles [64 k][64 n]

// Warp computes a 32x32 output tile over a 64-deep k reduction.
__device__ __forceinline__ void warp_mma_64k(const float* __restrict__ Xs,
                                             const float* __restrict__ Ws,
                                             int ro, int co, int lane,
                                             float acc[2][4][4]) {
    int gid = lane >> 2, tig = lane & 3;
#pragma unroll
    for (int kk = 0; kk < 64; kk += 8) {
        uint32_t a[2][4];
#pragma unroll
        for (int mi = 0; mi < 2; mi++) {
            const float* base = Xs + (ro + mi * 16 + gid) * XPAD + kk + tig;
            a[mi][0] = __float_as_uint(base[0]);
            a[mi][1] = __float_as_uint(base[8 * XPAD]);
            a[mi][2] = __float_as_uint(base[4]);
            a[mi][3] = __float_as_uint(base[8 * XPAD + 4]);
        }
#pragma unroll
        for (int ni = 0; ni < 4; ni++) {
            const float* wb = Ws + (kk + tig) * WPAD + co + ni * 8 + gid;
            uint32_t b0 = __float_as_uint(wb[0]);
            uint32_t b1 = __float_as_uint(wb[4 * WPAD]);
#pragma unroll
            for (int mi = 0; mi < 2; mi++)
                mma_tf32(acc[mi][ni], a[mi][0], a[mi][1], a[mi][2], a[mi][3],
                         b0, b1);
        }
    }
}

// ---------------------------------------------------------------------------
// Input GEMM (tf32): C[64-row tile, 64] = A[.,1024] @ B[1024,64]
// ---------------------------------------------------------------------------
__device__ __forceinline__ void gemm_in_tf32(const float* __restrict__ A,
                                             const float* __restrict__ B,
                                             float* __restrict__ C, int bx) {
    __shared__ float As[64 * XPAD];
    __shared__ float Bs[64 * WPAD];

    int tid = threadIdx.x;
    int w = tid >> 5, lane = tid & 31;
    int wr = w & 1, wc = w >> 1;
    int rb = bx * 64;

    float acc[2][4][4];
#pragma unroll
    for (int mi = 0; mi < 2; mi++)
#pragma unroll
        for (int ni = 0; ni < 4; ni++)
#pragma unroll
            for (int q = 0; q < 4; q++) acc[mi][ni][q] = 0.f;

    for (int k0 = 0; k0 < DIN; k0 += 64) {
#pragma unroll
        for (int i = 0; i < 8; i++) {
            int chunk = tid + 128 * i;
            int r = chunk >> 4, k4 = (chunk & 15) << 2;
            int gr = rb + r;
            float4 v = (gr < NN)
                ? __ldg((const float4*)&A[(size_t)gr * DIN + k0 + k4])
                : make_float4(0.f, 0.f, 0.f, 0.f);
            *(float4*)&As[r * XPAD + k4] = tf32r4(v);
        }
#pragma unroll
        for (int i = 0; i < 8; i++) {
            int chunk = tid + 128 * i;
            int k = chunk >> 4, n4 = (chunk & 15) << 2;
            float4 v = __ldg((const float4*)&B[(size_t)(k0 + k) * DOU + n4]);
            *(float4*)&Bs[k * WPAD + n4] = tf32r4(v);
        }
        __syncthreads();
        warp_mma_64k(As, Bs, wr * 32, wc * 32, lane, acc);
        __syncthreads();
    }

    int gid = lane >> 2, tig = lane & 3;
#pragma unroll
    for (int mi = 0; mi < 2; mi++) {
#pragma unroll
        for (int ni = 0; ni < 4; ni++) {
            int r0 = rb + wr * 32 + mi * 16 + gid;
            int c  = wc * 32 + ni * 8 + tig * 2;
            if (r0 < NN)
                *(float2*)&C[(size_t)r0 * DOU + c] =
                    make_float2(acc[mi][ni][0], acc[mi][ni][1]);
            if (r0 + 8 < NN)
                *(float2*)&C[(size_t)(r0 + 8) * DOU + c] =
                    make_float2(acc[mi][ni][2], acc[mi][ni][3]);
        }
    }
}

#define GEMM_BLKS 313   // ceil(20000/64)
#define ZERO_BLKS 256

// Phase 1: z0 = feat@W1 ; za0 = feat_a@W1 ; zero the 4 accumulators
__global__ __launch_bounds__(128) void k_phase1(
        const float* __restrict__ feat, const float* __restrict__ feat_a,
        const float* __restrict__ W1,
        float* __restrict__ z0, float* __restrict__ za0,
        float4* __restrict__ zout, float4* __restrict__ zaacc,
        float4* __restrict__ zsacc, float4* __restrict__ t) {
    int b = blockIdx.x;
    if (b < GEMM_BLKS) {
        gemm_in_tf32(feat, W1, z0, b);
    } else if (b < 2 * GEMM_BLKS) {
        gemm_in_tf32(feat_a, W1, za0, b - GEMM_BLKS);
    } else {
        int i = (b - 2 * GEMM_BLKS) * 128 + threadIdx.x;
        int stride = ZERO_BLKS * 128;
        float4 zv = make_float4(0.f, 0.f, 0.f, 0.f);
        for (int j = i; j < SZ / 4; j += stride) {
            zout[j] = zv; zaacc[j] = zv; zsacc[j] = zv; t[j] = zv;
        }
    }
}

// ---------------------------------------------------------------------------
// SpMM bodies (16 threads/edge, red.global.add.v4)
// ---------------------------------------------------------------------------
__device__ __forceinline__ void spmm_dual_body(unsigned idx,
        const int* __restrict__ row, const int* __restrict__ col,
        const float* __restrict__ vals,
        const float* __restrict__ x1, float* y1,
        const float* __restrict__ x2, float* y2) {
    unsigned e = idx >> 4;
    if (e >= NE) return;
    int lane4 = (idx & 15) << 2;
    int r = __ldg(&row[e]), c = __ldg(&col[e]);
    float v = __ldg(&vals[e]);

    const float4 a = __ldg((const float4*)&x1[(size_t)c * DOU + lane4]);
    red4(&y1[(size_t)r * DOU + lane4], v * a.x, v * a.y, v * a.z, v * a.w);

    const float4 bb = __ldg((const float4*)&x2[(size_t)c * DOU + lane4]);
    red4(&y2[(size_t)r * DOU + lane4], v * bb.x, v * bb.y, v * bb.z, v * bb.w);
}

__device__ __forceinline__ void spmm_single_body(unsigned idx,
        const int* __restrict__ row, const int* __restrict__ col,
        const float* __restrict__ vals,
        const float* __restrict__ x1, float* y1) {
    unsigned e = idx >> 4;
    if (e >= NE) return;
    int lane4 = (idx & 15) << 2;
    int r = __ldg(&row[e]), c = __ldg(&col[e]);
    float v = __ldg(&vals[e]);

    const float4 a = __ldg((const float4*)&x1[(size_t)c * DOU + lane4]);
    red4(&y1[(size_t)r * DOU + lane4], v * a.x, v * a.y, v * a.z, v * a.w);
}

#define SP_BLKS 20000   // NE*16/256

// Phase 2: z = A z0, zaacc = A za0  ||  zsacc = A_a za0
__global__ __launch_bounds__(256) void k_phase2(
        const int* __restrict__ row,  const int* __restrict__ col,
        const float* __restrict__ vals,
        const int* __restrict__ row_a, const int* __restrict__ col_a,
        const float* __restrict__ vals_a,
        const float* __restrict__ z0, const float* __restrict__ za0,
        float* __restrict__ zout, float* __restrict__ zaacc,
        float* __restrict__ zsacc) {
    int b = blockIdx.x;
    if (b < SP_BLKS) {
        unsigned idx = (unsigned)b * 256u + threadIdx.x;
        spmm_dual_body(idx, row, col, vals, z0, zout, za0, zaacc);
    } else {
        unsigned idx = (unsigned)(b - SP_BLKS) * 256u + threadIdx.x;
        spmm_single_body(idx, row_a, col_a, vals_a, za0, zsacc);
    }
}

#define BI_BLKS 2500   // NN/8

// Phase 3: t = A z  ||  bilinear discriminators
__global__ __launch_bounds__(256) void k_phase3(
        const int* __restrict__ row, const int* __restrict__ col,
        const float* __restrict__ vals,
        const float* __restrict__ z, float* __restrict__ t,
        const float* __restrict__ za, const float* __restrict__ zsv,
        const float* __restrict__ W, const float* __restrict__ bptr,
        float* __restrict__ ret, float* __restrict__ reta) {
    int b = blockIdx.x;
    if (b < SP_BLKS) {
        unsigned idx = (unsigned)b * 256u + threadIdx.x;
        spmm_single_body(idx, row, col, vals, z, t);
    } else {
        __shared__ float Ws[64 * 65];
        __shared__ float ce[8][64], ca[8][64], cs[8][64];

        int tid = threadIdx.x;
        for (int idx = tid; idx < 4096; idx += 256) {
            int d = idx >> 6, k = idx & 63;
            Ws[d * 65 + k] = W[idx];
        }

        int w = tid >> 5, lane = tid & 31;
        int rowb = (b - SP_BLKS) * 8 + w;

#pragma unroll
        for (int jj = 0; jj < 2; jj++) {
            int j = lane + jj * 32;
            ce[w][j] = fmaxf(z  [(size_t)rowb * DOU + j], 0.f);
            ca[w][j] = fmaxf(za [(size_t)rowb * DOU + j], 0.f);
            cs[w][j] = fmaxf(zsv[(size_t)rowb * DOU + j], 0.f);
        }
        __syncthreads();

        float r1 = 0.f, r2 = 0.f;
#pragma unroll
        for (int dd = 0; dd < 2; dd++) {
            int d = lane + dd * 32;
            float s1 = 0.f, s2 = 0.f;
#pragma unroll
            for (int k = 0; k < 64; k++) {
                float wv = Ws[d * 65 + k];
                s1 = fmaf(wv, ce[w][k], s1);
                s2 = fmaf(wv, ca[w][k], s2);
            }
            r1 = fmaf(ca[w][d], s1, r1);
            r2 = fmaf(cs[w][d], s2, r2);
        }
#pragma unroll
        for (int off = 16; off; off >>= 1) {
            r1 += __shfl_down_sync(0xffffffffu, r1, off);
            r2 += __shfl_down_sync(0xffffffffu, r2, off);
        }
        if (lane == 0) {
            float bv = bptr[0];
            ret[rowb]  = r1 + bv;
            reta[rowb] = r2 + bv;
        }
    }
}

// ---------------------------------------------------------------------------
// Phase 4 (tf32 tensor): block computes rows[rb,rb+64) x cols[cb,cb+64) of
// BOTH h = T@W2 and zinb = Z0@W2 (-> mean/disp), sharing the W2 smem tile.
// Epilogue stages results through smem (reusing the Ts region) so every gmem
// store is a per-warp-contiguous float4 row segment (full 128B lines).
// ---------------------------------------------------------------------------
#define WIDE_SMEM ((2 * 64 * XPAD + 64 * WPAD) * 4)   // 53248 bytes

__global__ __launch_bounds__(256) void k_wide(
        const float* __restrict__ T, const float* __restrict__ Z0,
        const float* __restrict__ W2,
        float* __restrict__ hout, float* __restrict__ meanout,
        float* __restrict__ dispout) {
    extern __shared__ float sm[];
    float* Ts = sm;
    float* Zs = sm + 64 * XPAD;
    float* Ws = sm + 2 * 64 * XPAD;

    int tid = threadIdx.x;
    int colTile = blockIdx.x & 15;
    int rowTile = blockIdx.x >> 4;
    int rb = rowTile * 64;
    int cb = colTile * 64;

    // stage T/Z tiles [64 rows][64 k]
#pragma unroll
    for (int i = 0; i < 4; i++) {
        int chunk = tid + 256 * i;
        int r = chunk >> 4, k4 = (chunk & 15) << 2;
        int gr = rb + r;
        float4 tv = make_float4(0.f, 0.f, 0.f, 0.f), zv = tv;
        if (gr < NN) {
            tv = __ldg((const float4*)&T [(size_t)gr * DOU + k4]);
            zv = __ldg((const float4*)&Z0[(size_t)gr * DOU + k4]);
        }
        *(float4*)&Ts[r * XPAD + k4] = tf32r4(tv);
        *(float4*)&Zs[r * XPAD + k4] = tf32r4(zv);
    }
    // stage W2 tile [64 k][64 n]
#pragma unroll
    for (int i = 0; i < 4; i++) {
        int chunk = tid + 256 * i;
        int k = chunk >> 4, n4 = (chunk & 15) << 2;
        float4 v = __ldg((const float4*)&W2[(size_t)k * DIN + cb + n4]);
        *(float4*)&Ws[k * WPAD + n4] = tf32r4(v);
    }
    __syncthreads();

    int w = tid >> 5, lane = tid & 31;
    int mat = w & 1, wr = (w >> 1) & 1, wc = w >> 2;
    const float* Xs = mat ? Zs : Ts;

    float acc[2][4][4];
#pragma unroll
    for (int mi = 0; mi < 2; mi++)
#pragma unroll
        for (int ni = 0; ni < 4; ni++)
#pragma unroll
            for (int q = 0; q < 4; q++) acc[mi][ni][q] = 0.f;

    warp_mma_64k(Xs, Ws, wr * 32, wc * 32, lane, acc);
    __syncthreads();   // everyone done reading Ts/Zs/Ws

    // Reuse Ts region as a [64][XPAD] staging tile
    float* S = sm;
    int gid = lane >> 2, tig = lane & 3;

    // ---- h: mat0 warps deposit accumulators, all threads stream out ----
    if (mat == 0) {
#pragma unroll
        for (int mi = 0; mi < 2; mi++)
#pragma unroll
            for (int ni = 0; ni < 4; ni++) {
                int r = wr * 32 + mi * 16 + gid;
                int c = wc * 32 + ni * 8 + tig * 2;
                *(float2*)&S[r * XPAD + c] =
                    make_float2(acc[mi][ni][0], acc[mi][ni][1]);
                *(float2*)&S[(r + 8) * XPAD + c] =
                    make_float2(acc[mi][ni][2], acc[mi][ni][3]);
            }
    }
    __syncthreads();
#pragma unroll
    for (int i = 0; i < 4; i++) {
        int chunk = tid + 256 * i;
        int r = chunk >> 4, c4 = (chunk & 15) << 2;
        int gr = rb + r;
        if (gr < NN)
            __stcs((float4*)&hout[(size_t)gr * DIN + cb + c4],
                   *(const float4*)&S[r * XPAD + c4]);
    }
    __syncthreads();

    // ---- zinb: mat1 warps deposit, all threads compute mean/disp out ----
    if (mat == 1) {
#pragma unroll
        for (int mi = 0; mi < 2; mi++)
#pragma unroll
            for (int ni = 0; ni < 4; ni++) {
                int r = wr * 32 + mi * 16 + gid;
                int c = wc * 32 + ni * 8 + tig * 2;
                *(float2*)&S[r * XPAD + c] =
                    make_float2(acc[mi][ni][0], acc[mi][ni][1]);
                *(float2*)&S[(r + 8) * XPAD + c] =
                    make_float2(acc[mi][ni][2], acc[mi][ni][3]);
            }
    }
    __syncthreads();
#pragma unroll
    for (int i = 0; i < 4; i++) {
        int chunk = tid + 256 * i;
        int r = chunk >> 4, c4 = (chunk & 15) << 2;
        int gr = rb + r;
        if (gr < NN) {
            float4 x = *(const float4*)&S[r * XPAD + c4];
            size_t o = (size_t)gr * DIN + cb + c4;
            float4 mv, dv;
            float* xp = &x.x; float* mp = &mv.x; float* dp = &dv.x;
#pragma unroll
            for (int c = 0; c < 4; c++) {
                mp[c] = fminf(fmaxf(__expf(xp[c]), 1e-5f), 1e6f);
                float sp = fmaxf(xp[c], 0.f) + __logf(1.f + __expf(-fabsf(xp[c])));
                dp[c] = fminf(fmaxf(sp, 1e-4f), 1e4f);
            }
            __stcs((float4*)&meanout[o], mv);
            __stcs((float4*)&dispout[o], dv);
        }
    }
}

// ---------------------------------------------------------------------------
extern "C" void kernel_launch(void* const* d_in, const int* in_sizes, int n_in,
                              void* d_out, int out_size) {
    const float* feat   = (const float*)d_in[0];
    const float* feat_a = (const float*)d_in[1];
    const int*   row    = (const int*)  d_in[2];
    const int*   col    = (const int*)  d_in[3];
    const float* vals   = (const float*)d_in[4];
    const int*   row_a  = (const int*)  d_in[5];
    const int*   col_a  = (const int*)  d_in[6];
    const float* vals_a = (const float*)d_in[7];
    const float* W1     = (const float*)d_in[8];
    const float* W2     = (const float*)d_in[9];
    const float* discW  = (const float*)d_in[10];
    const float* discB  = (const float*)d_in[11];

    float* out = (float*)d_out;
    float* z_out    = out + OFF_HIDEN;
    float* h_out    = out + OFF_H;
    float* ret_out  = out + OFF_RET;
    float* reta_out = out + OFF_RETA;
    float* mean_out = out + OFF_MEAN;
    float* disp_out = out + OFF_DISP;

    float *p_z0, *p_za0, *p_zaacc, *p_zsacc, *p_t;
    cudaGetSymbolAddress((void**)&p_z0,    g_z0);
    cudaGetSymbolAddress((void**)&p_za0,   g_za0);
    cudaGetSymbolAddress((void**)&p_zaacc, g_zaacc);
    cudaGetSymbolAddress((void**)&p_zsacc, g_zsacc);
    cudaGetSymbolAddress((void**)&p_t,     g_t);

    static int smem_set = 0;
    if (!smem_set) {
        cudaFuncSetAttribute(k_wide, cudaFuncAttributeMaxDynamicSharedMemorySize,
                             WIDE_SMEM);
        smem_set = 1;
    }

    // 1. z0/za0 GEMMs (tf32 tensor) + zero accumulators
    k_phase1<<<2 * GEMM_BLKS + ZERO_BLKS, 128>>>(
        feat, feat_a, W1, p_z0, p_za0,
        (float4*)z_out, (float4*)p_zaacc, (float4*)p_zsacc, (float4*)p_t);

    // 2. spmm_dual(A: z0->z, za0->zaacc) || spmm(A_a: za0->zsacc)
    k_phase2<<<2 * SP_BLKS, 256>>>(
        row, col, vals, row_a, col_a, vals_a,
        p_z0, p_za0, z_out, p_zaacc, p_zsacc);

    // 3. t = A z || bilinear discriminators
    k_phase3<<<SP_BLKS + BI_BLKS, 256>>>(
        row, col, vals, z_out, p_t,
        p_zaacc, p_zsacc, discW, discB, ret_out, reta_out);

    // 4. h = t@W2 and mean/disp from z0@W2 (tf32 tensor, shared W2 tile)
    k_wide<<<313 * 16, 256, WIDE_SMEM>>>(p_t, p_z0, W2,
                                         h_out, mean_out, disp_out);
}